// round 17
// baseline (speedup 1.0000x reference)
#include <cuda_runtime.h>
#include <cuda_bf16.h>
#include <cstdint>

// GaussianKernel: N=32, R=128, F=128
// Gram form: D[i,j] = ||u_i||^2 - 2 u_i.v_j + ||v_j||^2,  u = x1 - mean, v = x2
// out = softmax_j( exp( exp(-D/(2 sigma^2)) ) )
//
// v17 = v16 (session best: ncu 9.568us) + two epilogue/fill trims:
//  - outer exp poly degree 10 -> 7 (abs err ~7e-5, ~50x inside 1e-3 budget)
//  - normu shfl trees 5 -> 3 levels (partials combined by the reader)
// 128 blocks (1/SM), 256 threads = 8 warps. 4i x 4j register tile per thread.

#define N_B 32
#define R_DIM 128
#define F_DIM 128
#define TIB 32
#define X2_STRIDE 132   // padded row stride (floats): conflict-free LDS.128

typedef unsigned long long ull;

__device__ __forceinline__ ull f32x2_fma(ull a, ull b, ull c) {
    ull r;
    asm("fma.rn.f32x2 %0, %1, %2, %3;" : "=l"(r) : "l"(a), "l"(b), "l"(c));
    return r;
}
__device__ __forceinline__ void f32x2_unpack(ull u, float& lo, float& hi) {
    asm("mov.b64 {%0, %1}, %2;" : "=f"(lo), "=f"(hi) : "l"(u));
}

// exp(x) for x in [0,1] (valid slightly past 1): scalar Taylor degree 7,
// Horner, FFMA-imm fast path. |err| <= ~6.7e-5 abs on [0,1].
__device__ __forceinline__ float exp01(float x) {
    float r = fmaf(1.98412698e-4f, x, 1.38888889e-3f);  // 1/7!, 1/6!
    r = fmaf(r, x, 8.33333333e-3f);                     // 1/5!
    r = fmaf(r, x, 4.16666667e-2f);                     // 1/4!
    r = fmaf(r, x, 1.66666667e-1f);                     // 1/3!
    r = fmaf(r, x, 0.5f);
    r = fmaf(r, x, 1.0f);
    r = fmaf(r, x, 1.0f);
    return r;
}

__global__ void __launch_bounds__(256)
gaussian_gram_v17(const float4* __restrict__ x1,
                  const float4* __restrict__ x2,
                  const float* __restrict__ sigma,
                  const float* __restrict__ mean,
                  float* __restrict__ out) {
    extern __shared__ float smem[];
    float* x2s = smem;                           // [128][132]  v
    float* x1s = x2s + R_DIM * X2_STRIDE;        // [32][128]   u = x1 - mean
    float* nup = x1s + TIB * F_DIM;              // [32][4]  u-norm group partials
    float* nvp = nup + TIB * 4;                  // [128][4] v-norm group partials

    const int n    = blockIdx.y;
    const int i0   = blockIdx.x * TIB;
    const int t    = threadIdx.x;
    const int lane = t & 31;
    const int warp = t >> 5;                     // 0..7 -> i-rows 4w..4w+3

    const float mn = mean[0];
    const float sg = sigma[0];
    const float inv2s2 = 1.0f / (2.0f * sg * sg);

    // ---- batched fill: ALL LDGs first (MLP=20), then STS + fused norms ----
    {
        const float4* x2g = x2 + (size_t)n * (R_DIM * F_DIM / 4);
        const float4* x1g = x1 + ((size_t)n * R_DIM + i0) * (F_DIM / 4);
        float4 vb[16], ub[4];
        #pragma unroll
        for (int it = 0; it < 16; ++it) vb[it] = x2g[t + 256 * it];
        #pragma unroll
        for (int it = 0; it < 4; ++it)  ub[it] = x1g[t + 256 * it];

        // x2 store + normv partials: warp holds FULL row per iter.
        // 3-level tree -> group-of-8 partials in lanes {0,8,16,24}.
        #pragma unroll
        for (int it = 0; it < 16; ++it) {
            int idx4 = t + 256 * it;
            int row  = idx4 >> 5;                // lane-invariant per warp
            int c4   = idx4 & 31;
            float4 v = vb[it];
            *(float4*)&x2s[row * X2_STRIDE + c4 * 4] = v;
            float sq = v.x * v.x;
            sq = fmaf(v.y, v.y, sq);
            sq = fmaf(v.z, v.z, sq);
            sq = fmaf(v.w, v.w, sq);
            sq += __shfl_xor_sync(0xffffffffu, sq, 1);
            sq += __shfl_xor_sync(0xffffffffu, sq, 2);
            sq += __shfl_xor_sync(0xffffffffu, sq, 4);
            if ((lane & 7) == 0) nvp[row * 4 + (lane >> 3)] = sq;
        }
        // x1 store (u = x - mean) + normu partials (3-level tree)
        #pragma unroll
        for (int it = 0; it < 4; ++it) {
            int idx4 = t + 256 * it;
            int row  = idx4 >> 5;                // 0..31
            float4 v = ub[it];
            float4 u = make_float4(v.x - mn, v.y - mn, v.z - mn, v.w - mn);
            *(float4*)&x1s[idx4 * 4] = u;
            float sq = u.x * u.x;
            sq = fmaf(u.y, u.y, sq);
            sq = fmaf(u.z, u.z, sq);
            sq = fmaf(u.w, u.w, sq);
            sq += __shfl_xor_sync(0xffffffffu, sq, 1);
            sq += __shfl_xor_sync(0xffffffffu, sq, 2);
            sq += __shfl_xor_sync(0xffffffffu, sq, 4);
            if ((lane & 7) == 0) nup[row * 4 + (lane >> 3)] = sq;
        }
    }
    __syncthreads();

    // ---- main loop: 4i x 4j tile, software-pipelined (prefetch dist 1) ----
    ull acc[4][4];
    #pragma unroll
    for (int r = 0; r < 4; ++r)
        #pragma unroll
        for (int q = 0; q < 4; ++q) acc[r][q] = 0ull;

    const ulonglong2* brow = (const ulonglong2*)&x2s[lane * X2_STRIDE];
    const float* arow = &x1s[warp * 4 * F_DIM];
    const int bq_stride = 32 * X2_STRIDE / 4;

    ulonglong2 bc[4], ac[4], bn[4], an[4];
    #pragma unroll
    for (int q = 0; q < 4; ++q) bc[q] = brow[q * bq_stride];
    #pragma unroll
    for (int r = 0; r < 4; ++r) ac[r] = *(const ulonglong2*)&arow[r * F_DIM];

    #pragma unroll 8
    for (int f4 = 0; f4 < F_DIM / 4; ++f4) {
        if (f4 + 1 < F_DIM / 4) {
            #pragma unroll
            for (int q = 0; q < 4; ++q) bn[q] = brow[q * bq_stride + f4 + 1];
            #pragma unroll
            for (int r = 0; r < 4; ++r) an[r] = *(const ulonglong2*)&arow[r * F_DIM + (f4 + 1) * 4];
        }
        #pragma unroll
        for (int r = 0; r < 4; ++r)
            #pragma unroll
            for (int q = 0; q < 4; ++q) {
                acc[r][q] = f32x2_fma(ac[r].x, bc[q].x, acc[r][q]);
                acc[r][q] = f32x2_fma(ac[r].y, bc[q].y, acc[r][q]);
            }
        #pragma unroll
        for (int q = 0; q < 4; ++q) bc[q] = bn[q];
        #pragma unroll
        for (int r = 0; r < 4; ++r) ac[r] = an[r];
    }

    // ---- epilogue: combine norm partials, kernel value, softmax ----
    float nv[4];
    #pragma unroll
    for (int q = 0; q < 4; ++q) {
        float4 p = *(const float4*)&nvp[(lane + 32 * q) * 4];
        nv[q] = (p.x + p.y) + (p.z + p.w);
    }
    float nu[4];
    #pragma unroll
    for (int r = 0; r < 4; ++r) {
        float4 p = *(const float4*)&nup[(warp * 4 + r) * 4];
        nu[r] = (p.x + p.y) + (p.z + p.w);
    }

    float* outbase = out + ((size_t)n * R_DIM + i0 + warp * 4) * R_DIM;

    #pragma unroll
    for (int r = 0; r < 4; ++r) {
        float ex[4];
        float s = 0.0f;
        #pragma unroll
        for (int q = 0; q < 4; ++q) {
            float lo, hi; f32x2_unpack(acc[r][q], lo, hi);
            float D = fmaf(-2.0f, lo + hi, nu[r] + nv[q]);
            float k = __expf(-D * inv2s2);       // in (0,1] (+~1e-5 rounding)
            ex[q] = exp01(k);                    // deg-7 poly, FFMA-imm path
            s += ex[q];
        }
        #pragma unroll
        for (int o = 16; o > 0; o >>= 1)
            s += __shfl_xor_sync(0xffffffffu, s, o);
        const float inv = __fdividef(1.0f, s);
        #pragma unroll
        for (int q = 0; q < 4; ++q)
            outbase[r * R_DIM + lane + 32 * q] = ex[q] * inv;
    }
}

extern "C" void kernel_launch(void* const* d_in, const int* in_sizes, int n_in,
                              void* d_out, int out_size) {
    const float4* x1    = (const float4*)d_in[0];
    const float4* x2    = (const float4*)d_in[1];
    const float*  sigma = (const float*)d_in[2];
    const float*  mean  = (const float*)d_in[3];
    float* out = (float*)d_out;

    const int smem_bytes = (R_DIM * X2_STRIDE + TIB * F_DIM + TIB * 4 + R_DIM * 4) * (int)sizeof(float);
    cudaFuncSetAttribute(gaussian_gram_v17,
                         cudaFuncAttributeMaxDynamicSharedMemorySize, smem_bytes);

    dim3 grid(R_DIM / TIB, N_B);   // (4, 32) = 128 blocks -> 1 per SM
    dim3 block(256);
    gaussian_gram_v17<<<grid, block, smem_bytes>>>(x1, x2, sigma, mean, out);
}